// round 11
// baseline (speedup 1.0000x reference)
#include <cuda_runtime.h>
#include <cuda_fp16.h>
#include <cstdint>
#include <math.h>

#define NH    16
#define DH    64
#define LSEQ  2048
#define NB    2
#define INNER 1024
#define QK_SCALE 0.125f

// Scratch (__device__ globals; allocation-free rule). All u32 = packed half2.
__device__ uint32_t g_qh2[(size_t)NB*NH*LSEQ*32];   // [bh][l][dh/2] half2 along dh
__device__ uint32_t g_kh2[(size_t)NB*NH*LSEQ*32];   // same
__device__ uint32_t g_vh2[(size_t)NB*NH*LSEQ*32];   // same
__device__ uint32_t g_zh2[(size_t)4096*512];        // [b*l][inner/2] half2 along inner
__device__ uint32_t g_xh2[(size_t)4096*512];        // [b*l][dim/2]  half2 along k
__device__ uint32_t g_wqh2[(size_t)512*3072];       // [k/2][3072]   half2 = k-pair
__device__ uint32_t g_woh2[(size_t)512*1024];       // [k/2][1024]   half2 = k-pair

// ---------------------------------------------------------------------------
// Helpers (sm_80-baseline; safe on plain sm_103 target)
// ---------------------------------------------------------------------------
__device__ __forceinline__ void mma16(float d[4], const uint32_t a[4],
                                      const uint32_t b[2]) {
    asm volatile(
        "mma.sync.aligned.m16n8k16.row.col.f32.f16.f16.f32 "
        "{%0,%1,%2,%3}, {%4,%5,%6,%7}, {%8,%9}, {%0,%1,%2,%3};"
        : "+f"(d[0]), "+f"(d[1]), "+f"(d[2]), "+f"(d[3])
        : "r"(a[0]), "r"(a[1]), "r"(a[2]), "r"(a[3]),
          "r"(b[0]), "r"(b[1]));
}
__device__ __forceinline__ uint32_t pack2(float lo, float hi) {
    __half2 h = __floats2half2_rn(lo, hi);
    return *(uint32_t*)&h;
}
__device__ __forceinline__ __half2 u2h(uint32_t v) {
    __half2 h; *(uint32_t*)&h = v; return h;
}
__device__ __forceinline__ uint32_t h2u(__half2 h) { return *(uint32_t*)&h; }
__device__ __forceinline__ uint32_t smem_u32(const void* p) {
    uint32_t a;
    asm("{ .reg .u64 t; cvta.to.shared.u64 t, %1; cvt.u32.u64 %0, t; }"
        : "=r"(a) : "l"(p));
    return a;
}
__device__ __forceinline__ void cp_async16(uint32_t dst, const void* src) {
    asm volatile("cp.async.ca.shared.global [%0], [%1], 16;"
                 :: "r"(dst), "l"(src) : "memory");
}
__device__ __forceinline__ void cp_commit() {
    asm volatile("cp.async.commit_group;" ::: "memory");
}
template <int N>
__device__ __forceinline__ void cp_wait() {
    asm volatile("cp.async.wait_group %0;" :: "n"(N) : "memory");
}

// ---------------------------------------------------------------------------
// Packing kernels (run once per launch; ~30MB total traffic)
// ---------------------------------------------------------------------------
__global__ void pack_pairs(const float* __restrict__ src, uint32_t* __restrict__ dst,
                           int n)
{
    int i = blockIdx.x * blockDim.x + threadIdx.x;
    if (i < n) {
        float2 v = ((const float2*)src)[i];
        dst[i] = pack2(v.x, v.y);
    }
}
__global__ void pack_rows(const float* __restrict__ src, uint32_t* __restrict__ dst,
                          int N, int n)
{
    int i = blockIdx.x * blockDim.x + threadIdx.x;
    if (i < n) {
        int kp = i / N, c = i - kp * N;
        dst[i] = pack2(src[(size_t)(2 * kp) * N + c],
                       src[(size_t)(2 * kp + 1) * N + c]);
    }
}

// ---------------------------------------------------------------------------
// fp16 GEMM, cp.async double-buffered. C[4096][Ncols] = A @ W.
// A2: [4096][512] u32 (half2 along k). W2: [512][Ncols] u32 (k-pair packed).
// 128 threads = 4 warps; block tile 64x64; K-tile 64 (2 half-k u32 * 32).
// mode 0: pack+scatter C to qh2/kh2/vh2. mode 1: C + bias -> fp32 out.
// ---------------------------------------------------------------------------
__global__ __launch_bounds__(128) void gemm_h2(const uint32_t* __restrict__ A2,
                                               const uint32_t* __restrict__ W2,
                                               const float* __restrict__ bias,
                                               float* __restrict__ outp,
                                               int Ncols, int mode)
{
    extern __shared__ uint32_t sh[];
    uint32_t* As[2] = { sh,                sh + 64 * 36 };
    uint32_t* Bs[2] = { sh + 2 * 64 * 36,  sh + 2 * 64 * 36 + 32 * 68 };

    const int tid  = threadIdx.x;
    const int lane = tid & 31;
    const int w    = tid >> 5;
    const int g    = lane >> 2;
    const int t    = lane & 3;
    const int m0   = blockIdx.y * 64;
    const int n0   = blockIdx.x * 64;
    const int rw   = w * 16;

    float acc[8][4];
    #pragma unroll
    for (int j = 0; j < 8; j++)
        #pragma unroll
        for (int r = 0; r < 4; r++) acc[j][r] = 0.f;

    auto stage = [&](int buf, int kt) {
        uint32_t sa = smem_u32(As[buf]);
        #pragma unroll
        for (int i = 0; i < 4; i++) {          // A: 64 rows x 32 u32
            int idx = tid + 128 * i;
            int r = idx >> 3, c4 = (idx & 7) * 4;
            cp_async16(sa + (uint32_t)(r * 36 + c4) * 4,
                       &A2[(size_t)(m0 + r) * 512 + kt * 32 + c4]);
        }
        uint32_t sb = smem_u32(Bs[buf]);
        #pragma unroll
        for (int i = 0; i < 4; i++) {          // B: 32 kpairs x 64 u32
            int idx = tid + 128 * i;
            int kp = idx >> 4, c4 = (idx & 15) * 4;
            cp_async16(sb + (uint32_t)(kp * 68 + c4) * 4,
                       &W2[(size_t)(kt * 32 + kp) * Ncols + n0 + c4]);
        }
        cp_commit();
    };

    stage(0, 0);

    #pragma unroll 1
    for (int kt = 0; kt < 16; kt++) {
        int cur = kt & 1;
        if (kt + 1 < 16) { stage(cur ^ 1, kt + 1); cp_wait<1>(); }
        else             { cp_wait<0>(); }
        __syncthreads();

        const uint32_t* Ac = As[cur];
        const uint32_t* Bc = Bs[cur];
        #pragma unroll
        for (int ks = 0; ks < 4; ks++) {
            uint32_t af[4];
            af[0] = Ac[(rw + g) * 36 + ks * 8 + t];
            af[1] = Ac[(rw + g + 8) * 36 + ks * 8 + t];
            af[2] = Ac[(rw + g) * 36 + ks * 8 + t + 4];
            af[3] = Ac[(rw + g + 8) * 36 + ks * 8 + t + 4];
            #pragma unroll
            for (int j = 0; j < 8; j++) {
                uint32_t bf[2];
                bf[0] = Bc[(ks * 8 + t) * 68 + j * 8 + g];
                bf[1] = Bc[(ks * 8 + t + 4) * 68 + j * 8 + g];
                mma16(acc[j], af, bf);
            }
        }
        __syncthreads();
    }

    int r_lo = m0 + rw + g;
    int r_hi = r_lo + 8;
    #pragma unroll
    for (int j = 0; j < 8; j++) {
        int n = n0 + j * 8 + 2 * t;
        if (mode == 1) {
            float2 o0 = { acc[j][0] + bias[n], acc[j][1] + bias[n + 1] };
            float2 o1 = { acc[j][2] + bias[n], acc[j][3] + bias[n + 1] };
            *(float2*)&outp[(size_t)r_lo * 1024 + n] = o0;
            *(float2*)&outp[(size_t)r_hi * 1024 + n] = o1;
        } else {
            int three = n >> 10, rem = n & 1023, hh = rem >> 6, dd = rem & 63;
            uint32_t* base = (three == 0) ? g_qh2 : (three == 1) ? g_kh2 : g_vh2;
            int bb_lo = r_lo >> 11, ll_lo = r_lo & 2047;
            int bb_hi = r_hi >> 11, ll_hi = r_hi & 2047;
            base[(((size_t)(bb_lo * NH + hh) * LSEQ) + ll_lo) * 32 + (dd >> 1)] =
                pack2(acc[j][0], acc[j][1]);
            base[(((size_t)(bb_hi * NH + hh) * LSEQ) + ll_hi) * 32 + (dd >> 1)] =
                pack2(acc[j][2], acc[j][3]);
        }
    }
}

// ---------------------------------------------------------------------------
// Attention, fp16 mma, packed inputs, cp.async K/mask staging.
// No-max exact softmax; scale folded into exp (fp32).
// ---------------------------------------------------------------------------
__global__ __launch_bounds__(128) void attn_mma(const float* __restrict__ mask,
                                                uint32_t* __restrict__ z2)
{
    extern __shared__ uint32_t sh[];
    uint32_t* Ks2 = sh;                      // [64 seq][36] half2 along dh
    uint32_t* Vs2 = Ks2 + 64 * 36;           // [32 seqpair][68] half2 = seq pair
    uint32_t* Ps2 = Vs2 + 32 * 68;           // [64 q][36] half2 along seq
    float*    Ms  = (float*)(Ps2 + 64 * 36); // [64 q][68] fp32 mask

    const int tid  = threadIdx.x;
    const int lane = tid & 31;
    const int w    = tid >> 5;
    const int g    = lane >> 2;
    const int t    = lane & 3;
    const int qb   = blockIdx.x;
    const int bh   = blockIdx.y;
    const int bb   = bh >> 4, hh = bh & 15;
    const int q0   = qb * 64;
    const int rw   = w * 16;

    const uint32_t* qp = g_qh2 + ((size_t)bh * LSEQ + q0) * 32;
    const uint32_t* kp = g_kh2 + (size_t)bh * LSEQ * 32;
    const uint32_t* vp = g_vh2 + (size_t)bh * LSEQ * 32;

    // Q fragments direct from packed gmem (no scale here; scale applied at exp)
    uint32_t qa[4][4];
    #pragma unroll
    for (int ks = 0; ks < 4; ks++) {
        const uint32_t* q_lo = qp + (rw + g) * 32;
        const uint32_t* q_hi = qp + (rw + g + 8) * 32;
        qa[ks][0] = q_lo[ks * 8 + t];
        qa[ks][1] = q_hi[ks * 8 + t];
        qa[ks][2] = q_lo[ks * 8 + t + 4];
        qa[ks][3] = q_hi[ks * 8 + t + 4];
    }

    float zacc[8][4];
    #pragma unroll
    for (int j = 0; j < 8; j++)
        #pragma unroll
        for (int r = 0; r < 4; r++) zacc[j][r] = 0.f;
    float sa_lo = 0.f, sa_hi = 0.f, sk_lo = 0.f, sk_hi = 0.f;

    const uint32_t sK = smem_u32(Ks2);
    const uint32_t sM = smem_u32(Ms);

    #pragma unroll 1
    for (int jt = 0; jt < LSEQ / 64; jt++) {
        __syncthreads();   // prior compute done reading all tiles
        // cp.async K tile: 64 rows x 32 u32
        #pragma unroll
        for (int i = 0; i < 4; i++) {
            int idx = tid + 128 * i;
            int r = idx >> 3, c4 = (idx & 7) * 4;
            cp_async16(sK + (uint32_t)(r * 36 + c4) * 4,
                       &kp[(size_t)(jt * 64 + r) * 32 + c4]);
        }
        // cp.async mask tile fp32: 64 rows x 64 floats
        #pragma unroll
        for (int i = 0; i < 8; i++) {
            int idx = tid + 128 * i;
            int r = idx >> 4, c4 = (idx & 15) * 4;
            cp_async16(sM + (uint32_t)(r * 68 + c4) * 4,
                       &mask[((size_t)bb * LSEQ + q0 + r) * LSEQ + jt * 64 + c4]);
        }
        cp_commit();
        // Manual V repack (overlaps with asyncs in flight): seq-pair interleave
        #pragma unroll
        for (int i = 0; i < 4; i++) {
            int idx = tid + 128 * i;            // 0..511
            int s = idx >> 4;                   // seq pair 0..31
            int c = (idx & 15) * 2;             // input u32 col (covers dh 2c..2c+3)
            const uint32_t* v0 = &vp[(size_t)(jt * 64 + 2 * s) * 32 + c];
            uint2 a = *(const uint2*)v0;        // row 2s
            uint2 b = *(const uint2*)(v0 + 32); // row 2s+1
            __half2 a0 = u2h(a.x), a1 = u2h(a.y), b0 = u2h(b.x), b1 = u2h(b.y);
            uint4 o = { h2u(__lows2half2(a0, b0)),  h2u(__highs2half2(a0, b0)),
                        h2u(__lows2half2(a1, b1)),  h2u(__highs2half2(a1, b1)) };
            *(uint4*)&Vs2[s * 68 + 2 * c] = o;  // dh cols 2c..2c+3
        }
        cp_wait<0>();
        __syncthreads();

        // S = Q K^T
        float sacc[8][4];
        #pragma unroll
        for (int j = 0; j < 8; j++)
            #pragma unroll
            for (int r = 0; r < 4; r++) sacc[j][r] = 0.f;
        #pragma unroll
        for (int ks = 0; ks < 4; ks++) {
            #pragma unroll
            for (int j = 0; j < 8; j++) {
                uint32_t bf[2];
                bf[0] = Ks2[(j * 8 + g) * 36 + ks * 8 + t];
                bf[1] = Ks2[(j * 8 + g) * 36 + ks * 8 + t + 4];
                mma16(sacc[j], qa[ks], bf);
            }
        }

        // exp(scale*s) + mask + row partial sums; write P (half2 along seq)
        #pragma unroll
        for (int j = 0; j < 8; j++) {
            float p0 = __expf(sacc[j][0] * QK_SCALE);
            float p1 = __expf(sacc[j][1] * QK_SCALE);
            float p2 = __expf(sacc[j][2] * QK_SCALE);
            float p3 = __expf(sacc[j][3] * QK_SCALE);
            float2 mlo = *(const float2*)&Ms[(rw + g) * 68 + j * 8 + 2 * t];
            float2 mhi = *(const float2*)&Ms[(rw + g + 8) * 68 + j * 8 + 2 * t];
            float w0 = p0 * mlo.x, w1 = p1 * mlo.y;
            float w2 = p2 * mhi.x, w3 = p3 * mhi.y;
            sa_lo += p0 + p1;  sa_hi += p2 + p3;
            sk_lo += w0 + w1;  sk_hi += w2 + w3;
            Ps2[(rw + g) * 36 + j * 4 + t]     = pack2(w0, w1);
            Ps2[(rw + g + 8) * 36 + j * 4 + t] = pack2(w2, w3);
        }
        __syncwarp();   // P rows are warp-private

        // zacc += P @ V
        #pragma unroll
        for (int ks = 0; ks < 4; ks++) {
            uint32_t pa[4];
            pa[0] = Ps2[(rw + g) * 36 + ks * 8 + t];
            pa[1] = Ps2[(rw + g + 8) * 36 + ks * 8 + t];
            pa[2] = Ps2[(rw + g) * 36 + ks * 8 + t + 4];
            pa[3] = Ps2[(rw + g + 8) * 36 + ks * 8 + t + 4];
            #pragma unroll
            for (int j = 0; j < 8; j++) {
                uint32_t bf[2];
                bf[0] = Vs2[(ks * 8 + t) * 68 + j * 8 + g];
                bf[1] = Vs2[(ks * 8 + t + 4) * 68 + j * 8 + g];
                mma16(zacc[j], pa, bf);
            }
        }
    }

    #pragma unroll
    for (int d = 1; d <= 2; d <<= 1) {
        sa_lo += __shfl_xor_sync(0xffffffffu, sa_lo, d);
        sa_hi += __shfl_xor_sync(0xffffffffu, sa_hi, d);
        sk_lo += __shfl_xor_sync(0xffffffffu, sk_lo, d);
        sk_hi += __shfl_xor_sync(0xffffffffu, sk_hi, d);
    }
    float inv_lo = 1.f / (sk_lo + 1e-10f * sa_lo);
    float inv_hi = 1.f / (sk_hi + 1e-10f * sa_hi);

    // z packed: [b*l][512] u32, col = (hh*64 + j*8 + 2t)/2
    size_t row_lo = (size_t)bb * LSEQ + q0 + rw + g;
    size_t row_hi = row_lo + 8;
    #pragma unroll
    for (int j = 0; j < 8; j++) {
        int c = hh * 32 + j * 4 + t;
        z2[row_lo * 512 + c] = pack2(zacc[j][0] * inv_lo, zacc[j][1] * inv_lo);
        z2[row_hi * 512 + c] = pack2(zacc[j][2] * inv_hi, zacc[j][3] * inv_hi);
    }
}

// ---------------------------------------------------------------------------
extern "C" void kernel_launch(void* const* d_in, const int* in_sizes, int n_in,
                              void* d_out, int out_size)
{
    const float* x     = (const float*)d_in[0];  // [2,2048,1024]
    const float* mask  = (const float*)d_in[1];  // [2,2048,2048]
    const float* W_qkv = (const float*)d_in[2];  // [1024,3072]
    const float* W_out = (const float*)d_in[3];  // [1024,1024]
    const float* b_out = (const float*)d_in[4];  // [1024]
    float* out = (float*)d_out;

    // One-time packing to fp16-half2 layouts
    pack_pairs<<<(4096 * 512 + 255) / 256, 256>>>(x, g_xh2, 4096 * 512);
    pack_rows<<<(512 * 3072 + 255) / 256, 256>>>(W_qkv, g_wqh2, 3072, 512 * 3072);
    pack_rows<<<(512 * 1024 + 255) / 256, 256>>>(W_out, g_woh2, 1024, 512 * 1024);

    const int gemm_smem = (2 * 64 * 36 + 2 * 32 * 68) * 4;   // 35840 B
    cudaFuncSetAttribute(gemm_h2, cudaFuncAttributeMaxDynamicSharedMemorySize, gemm_smem);

    // QKV projection -> packed q/k/v
    gemm_h2<<<dim3(3072 / 64, 4096 / 64), 128, gemm_smem>>>(
        g_xh2, g_wqh2, nullptr, nullptr, 3072, 0);

    // Attention -> packed z
    const int attn_smem = (64 * 36 + 32 * 68 + 64 * 36 + 64 * 68) * 4;  // 44544 B
    cudaFuncSetAttribute(attn_mma, cudaFuncAttributeMaxDynamicSharedMemorySize, attn_smem);
    attn_mma<<<dim3(LSEQ / 64, NB * NH), 128, attn_smem>>>(mask, g_zh2);

    // Output projection + bias -> fp32 out
    gemm_h2<<<dim3(1024 / 64, 4096 / 64), 128, gemm_smem>>>(
        g_zh2, g_woh2, b_out, out, 1024, 1);
}

// round 12
// speedup vs baseline: 1.1729x; 1.1729x over previous
#include <cuda_runtime.h>
#include <cuda_fp16.h>
#include <cstdint>
#include <math.h>

#define NH    16
#define DH    64
#define LSEQ  2048
#define NB    2
#define INNER 1024
#define QK_SCALE 0.125f

// Scratch (__device__ globals; allocation-free rule). u32 = packed half2.
__device__ uint32_t g_qh2[(size_t)NB*NH*LSEQ*32];   // [bh][l][dh/2] half2 along dh
__device__ uint32_t g_kh2[(size_t)NB*NH*LSEQ*32];
__device__ uint32_t g_vh2[(size_t)NB*NH*LSEQ*32];
__device__ uint32_t g_zh2[(size_t)4096*512];        // [b*l][inner/2] half2 along inner
__device__ uint32_t g_xh2[(size_t)4096*512];        // [b*l][dim/2]  half2 along k
__device__ uint32_t g_wqh2[(size_t)512*3072];       // [k/2][3072]   half2 = k-pair
__device__ uint32_t g_woh2[(size_t)512*1024];       // [k/2][1024]   half2 = k-pair

// ---------------------------------------------------------------------------
// Helpers (sm_80-baseline; safe on plain sm_103 target). NO cp.async.
// ---------------------------------------------------------------------------
__device__ __forceinline__ void mma16(float d[4], const uint32_t a[4],
                                      const uint32_t b[2]) {
    asm volatile(
        "mma.sync.aligned.m16n8k16.row.col.f32.f16.f16.f32 "
        "{%0,%1,%2,%3}, {%4,%5,%6,%7}, {%8,%9}, {%0,%1,%2,%3};"
        : "+f"(d[0]), "+f"(d[1]), "+f"(d[2]), "+f"(d[3])
        : "r"(a[0]), "r"(a[1]), "r"(a[2]), "r"(a[3]),
          "r"(b[0]), "r"(b[1]));
}
__device__ __forceinline__ uint32_t pack2(float lo, float hi) {
    __half2 h = __floats2half2_rn(lo, hi);
    return *(uint32_t*)&h;
}
__device__ __forceinline__ __half2 u2h(uint32_t v) {
    __half2 h; *(uint32_t*)&h = v; return h;
}
__device__ __forceinline__ uint32_t h2u(__half2 h) { return *(uint32_t*)&h; }

// ---------------------------------------------------------------------------
// Packing kernels (once per launch; ~30MB traffic, HBM-bound, ~10us)
// ---------------------------------------------------------------------------
__global__ void pack_pairs(const float* __restrict__ src, uint32_t* __restrict__ dst,
                           int n)
{
    int i = blockIdx.x * blockDim.x + threadIdx.x;
    if (i < n) {
        float2 v = ((const float2*)src)[i];
        dst[i] = pack2(v.x, v.y);
    }
}
__global__ void pack_rows(const float* __restrict__ src, uint32_t* __restrict__ dst,
                          int N, int n)
{
    int i = blockIdx.x * blockDim.x + threadIdx.x;
    if (i < n) {
        int kp = i / N, c = i - kp * N;
        dst[i] = pack2(src[(size_t)(2 * kp) * N + c],
                       src[(size_t)(2 * kp + 1) * N + c]);
    }
}

// ---------------------------------------------------------------------------
// fp16 GEMM with register double-buffering (plain LDG). C[4096][Ncols] = A @ W.
// A2: [4096][512] u32 (half2 along k). W2: [512][Ncols] u32 (k-pair packed).
// 128 threads = 4 warps; block tile 64x64; K-tile 64 (32 kpairs).
// mode 0: pack+scatter C to qh2/kh2/vh2. mode 1: C + bias -> fp32 out.
// ---------------------------------------------------------------------------
__global__ __launch_bounds__(128) void gemm_h2(const uint32_t* __restrict__ A2,
                                               const uint32_t* __restrict__ W2,
                                               const float* __restrict__ bias,
                                               float* __restrict__ outp,
                                               int Ncols, int mode)
{
    extern __shared__ uint32_t sh[];
    uint32_t* As = sh;              // [64 m][36] u32
    uint32_t* Bs = sh + 64 * 36;    // [32 kpair][68] u32

    const int tid  = threadIdx.x;
    const int lane = tid & 31;
    const int w    = tid >> 5;
    const int g    = lane >> 2;
    const int t    = lane & 3;
    const int m0   = blockIdx.y * 64;
    const int n0   = blockIdx.x * 64;
    const int rw   = w * 16;

    float acc[8][4];
    #pragma unroll
    for (int j = 0; j < 8; j++)
        #pragma unroll
        for (int r = 0; r < 4; r++) acc[j][r] = 0.f;

    uint4 pa[4], pb[4];
    auto ldg_tile = [&](int kt) {
        #pragma unroll
        for (int i = 0; i < 4; i++) {
            int idx = tid + 128 * i;
            int r = idx >> 3, c4 = (idx & 7) * 4;
            pa[i] = *(const uint4*)&A2[(size_t)(m0 + r) * 512 + kt * 32 + c4];
        }
        #pragma unroll
        for (int i = 0; i < 4; i++) {
            int idx = tid + 128 * i;
            int kp = idx >> 4, c4 = (idx & 15) * 4;
            pb[i] = *(const uint4*)&W2[(size_t)(kt * 32 + kp) * Ncols + n0 + c4];
        }
    };

    ldg_tile(0);

    #pragma unroll 1
    for (int kt = 0; kt < 16; kt++) {
        __syncthreads();     // everyone done reading smem from prior iter
        #pragma unroll
        for (int i = 0; i < 4; i++) {
            int idx = tid + 128 * i;
            int r = idx >> 3, c4 = (idx & 7) * 4;
            *(uint4*)&As[r * 36 + c4] = pa[i];
        }
        #pragma unroll
        for (int i = 0; i < 4; i++) {
            int idx = tid + 128 * i;
            int kp = idx >> 4, c4 = (idx & 15) * 4;
            *(uint4*)&Bs[kp * 68 + c4] = pb[i];
        }
        __syncthreads();
        if (kt + 1 < 16) ldg_tile(kt + 1);   // LDG latency hidden by mma below

        #pragma unroll
        for (int ks = 0; ks < 4; ks++) {
            uint32_t af[4];
            af[0] = As[(rw + g) * 36 + ks * 8 + t];
            af[1] = As[(rw + g + 8) * 36 + ks * 8 + t];
            af[2] = As[(rw + g) * 36 + ks * 8 + t + 4];
            af[3] = As[(rw + g + 8) * 36 + ks * 8 + t + 4];
            #pragma unroll
            for (int j = 0; j < 8; j++) {
                uint32_t bf[2];
                bf[0] = Bs[(ks * 8 + t) * 68 + j * 8 + g];
                bf[1] = Bs[(ks * 8 + t + 4) * 68 + j * 8 + g];
                mma16(acc[j], af, bf);
            }
        }
    }

    int r_lo = m0 + rw + g;
    int r_hi = r_lo + 8;
    #pragma unroll
    for (int j = 0; j < 8; j++) {
        int n = n0 + j * 8 + 2 * t;
        if (mode == 1) {
            float2 o0 = { acc[j][0] + bias[n], acc[j][1] + bias[n + 1] };
            float2 o1 = { acc[j][2] + bias[n], acc[j][3] + bias[n + 1] };
            *(float2*)&outp[(size_t)r_lo * 1024 + n] = o0;
            *(float2*)&outp[(size_t)r_hi * 1024 + n] = o1;
        } else {
            int three = n >> 10, rem = n & 1023, hh = rem >> 6, dd = rem & 63;
            uint32_t* base = (three == 0) ? g_qh2 : (three == 1) ? g_kh2 : g_vh2;
            int bb_lo = r_lo >> 11, ll_lo = r_lo & 2047;
            int bb_hi = r_hi >> 11, ll_hi = r_hi & 2047;
            base[(((size_t)(bb_lo * NH + hh) * LSEQ) + ll_lo) * 32 + (dd >> 1)] =
                pack2(acc[j][0], acc[j][1]);
            base[(((size_t)(bb_hi * NH + hh) * LSEQ) + ll_hi) * 32 + (dd >> 1)] =
                pack2(acc[j][2], acc[j][3]);
        }
    }
}

// ---------------------------------------------------------------------------
// Attention, fp16 mma, packed inputs, register double-buffered staging.
// No-max exact softmax; scale folded into exp (fp32).
// ---------------------------------------------------------------------------
__global__ __launch_bounds__(128) void attn_mma(const float* __restrict__ mask,
                                                uint32_t* __restrict__ z2)
{
    extern __shared__ uint32_t sh[];
    uint32_t* Ks2 = sh;                      // [64 seq][36] half2 along dh
    uint32_t* Vs2 = Ks2 + 64 * 36;           // [32 seqpair][68] half2 = seq pair
    uint32_t* Ps2 = Vs2 + 32 * 68;           // [64 q][36] half2 along seq
    float*    Ms  = (float*)(Ps2 + 64 * 36); // [64 q][68] fp32 mask

    const int tid  = threadIdx.x;
    const int lane = tid & 31;
    const int w    = tid >> 5;
    const int g    = lane >> 2;
    const int t    = lane & 3;
    const int qb   = blockIdx.x;
    const int bh   = blockIdx.y;
    const int bb   = bh >> 4, hh = bh & 15;
    const int q0   = qb * 64;
    const int rw   = w * 16;

    const uint32_t* qp = g_qh2 + ((size_t)bh * LSEQ + q0) * 32;
    const uint32_t* kp = g_kh2 + (size_t)bh * LSEQ * 32;
    const uint32_t* vp = g_vh2 + (size_t)bh * LSEQ * 32;
    const float*    mp = mask + (size_t)bb * LSEQ * LSEQ + (size_t)q0 * LSEQ;

    // Q fragments direct from packed gmem (scale applied later at exp)
    uint32_t qa[4][4];
    #pragma unroll
    for (int ks = 0; ks < 4; ks++) {
        const uint32_t* q_lo = qp + (rw + g) * 32;
        const uint32_t* q_hi = qp + (rw + g + 8) * 32;
        qa[ks][0] = q_lo[ks * 8 + t];
        qa[ks][1] = q_hi[ks * 8 + t];
        qa[ks][2] = q_lo[ks * 8 + t + 4];
        qa[ks][3] = q_hi[ks * 8 + t + 4];
    }

    float zacc[8][4];
    #pragma unroll
    for (int j = 0; j < 8; j++)
        #pragma unroll
        for (int r = 0; r < 4; r++) zacc[j][r] = 0.f;
    float sa_lo = 0.f, sa_hi = 0.f, sk_lo = 0.f, sk_hi = 0.f;

    // Prefetch registers for K (16 u32), V (16 u32), mask (32 f32)
    uint4  ka[4];
    uint2  va[4], vb[4];
    float4 ma[8];
    auto ldg_tiles = [&](int jt) {
        #pragma unroll
        for (int i = 0; i < 4; i++) {
            int idx = tid + 128 * i;
            int r = idx >> 3, c4 = (idx & 7) * 4;
            ka[i] = *(const uint4*)&kp[(size_t)(jt * 64 + r) * 32 + c4];
        }
        #pragma unroll
        for (int i = 0; i < 4; i++) {
            int idx = tid + 128 * i;
            int s = idx >> 4, c = (idx & 15) * 2;
            const uint32_t* v0 = &vp[(size_t)(jt * 64 + 2 * s) * 32 + c];
            va[i] = *(const uint2*)v0;
            vb[i] = *(const uint2*)(v0 + 32);
        }
        #pragma unroll
        for (int i = 0; i < 8; i++) {
            int idx = tid + 128 * i;
            int r = idx >> 4, c4 = (idx & 15) * 4;
            ma[i] = *(const float4*)&mp[(size_t)r * LSEQ + jt * 64 + c4];
        }
    };

    ldg_tiles(0);

    #pragma unroll 1
    for (int jt = 0; jt < LSEQ / 64; jt++) {
        __syncthreads();     // prior compute done reading tiles
        #pragma unroll
        for (int i = 0; i < 4; i++) {
            int idx = tid + 128 * i;
            int r = idx >> 3, c4 = (idx & 7) * 4;
            *(uint4*)&Ks2[r * 36 + c4] = ka[i];
        }
        #pragma unroll
        for (int i = 0; i < 4; i++) {
            int idx = tid + 128 * i;
            int s = idx >> 4, c = (idx & 15) * 2;
            __half2 a0 = u2h(va[i].x), a1 = u2h(va[i].y);
            __half2 b0 = u2h(vb[i].x), b1 = u2h(vb[i].y);
            uint4 o = { h2u(__lows2half2(a0, b0)),  h2u(__highs2half2(a0, b0)),
                        h2u(__lows2half2(a1, b1)),  h2u(__highs2half2(a1, b1)) };
            *(uint4*)&Vs2[s * 68 + 2 * c] = o;
        }
        #pragma unroll
        for (int i = 0; i < 8; i++) {
            int idx = tid + 128 * i;
            int r = idx >> 4, c4 = (idx & 15) * 4;
            *(float4*)&Ms[r * 68 + c4] = ma[i];
        }
        __syncthreads();
        if (jt + 1 < LSEQ / 64) ldg_tiles(jt + 1);   // hidden by compute below

        // S = Q K^T
        float sacc[8][4];
        #pragma unroll
        for (int j = 0; j < 8; j++)
            #pragma unroll
            for (int r = 0; r < 4; r++) sacc[j][r] = 0.f;
        #pragma unroll
        for (int ks = 0; ks < 4; ks++) {
            #pragma unroll
            for (int j = 0; j < 8; j++) {
                uint32_t bf[2];
                bf[0] = Ks2[(j * 8 + g) * 36 + ks * 8 + t];
                bf[1] = Ks2[(j * 8 + g) * 36 + ks * 8 + t + 4];
                mma16(sacc[j], qa[ks], bf);
            }
        }

        // exp(scale*s) + mask + row partial sums; write P (half2 along seq)
        #pragma unroll
        for (int j = 0; j < 8; j++) {
            float p0 = __expf(sacc[j][0] * QK_SCALE);
            float p1 = __expf(sacc[j][1] * QK_SCALE);
            float p2 = __expf(sacc[j][2] * QK_SCALE);
            float p3 = __expf(sacc[j][3] * QK_SCALE);
            float2 mlo = *(const float2*)&Ms[(rw + g) * 68 + j * 8 + 2 * t];
            float2 mhi = *(const float2*)&Ms[(rw + g + 8) * 68 + j * 8 + 2 * t];
            float w0 = p0 * mlo.x, w1 = p1 * mlo.y;
            float w2 = p2 * mhi.x, w3 = p3 * mhi.y;
            sa_lo += p0 + p1;  sa_hi += p2 + p3;
            sk_lo += w0 + w1;  sk_hi += w2 + w3;
            Ps2[(rw + g) * 36 + j * 4 + t]     = pack2(w0, w1);
            Ps2[(rw + g + 8) * 36 + j * 4 + t] = pack2(w2, w3);
        }
        __syncwarp();   // P rows are warp-private

        // zacc += P @ V
        #pragma unroll
        for (int ks = 0; ks < 4; ks++) {
            uint32_t pa4[4];
            pa4[0] = Ps2[(rw + g) * 36 + ks * 8 + t];
            pa4[1] = Ps2[(rw + g + 8) * 36 + ks * 8 + t];
            pa4[2] = Ps2[(rw + g) * 36 + ks * 8 + t + 4];
            pa4[3] = Ps2[(rw + g + 8) * 36 + ks * 8 + t + 4];
            #pragma unroll
            for (int j = 0; j < 8; j++) {
                uint32_t bf[2];
                bf[0] = Vs2[(ks * 8 + t) * 68 + j * 8 + g];
                bf[1] = Vs2[(ks * 8 + t + 4) * 68 + j * 8 + g];
                mma16(zacc[j], pa4, bf);
            }
        }
    }

    #pragma unroll
    for (int d = 1; d <= 2; d <<= 1) {
        sa_lo += __shfl_xor_sync(0xffffffffu, sa_lo, d);
        sa_hi += __shfl_xor_sync(0xffffffffu, sa_hi, d);
        sk_lo += __shfl_xor_sync(0xffffffffu, sk_lo, d);
        sk_hi += __shfl_xor_sync(0xffffffffu, sk_hi, d);
    }
    float inv_lo = 1.f / (sk_lo + 1e-10f * sa_lo);
    float inv_hi = 1.f / (sk_hi + 1e-10f * sa_hi);

    size_t row_lo = (size_t)bb * LSEQ + q0 + rw + g;
    size_t row_hi = row_lo + 8;
    #pragma unroll
    for (int j = 0; j < 8; j++) {
        int c = hh * 32 + j * 4 + t;
        z2[row_lo * 512 + c] = pack2(zacc[j][0] * inv_lo, zacc[j][1] * inv_lo);
        z2[row_hi * 512 + c] = pack2(zacc[j][2] * inv_hi, zacc[j][3] * inv_hi);
    }
}

// ---------------------------------------------------------------------------
extern "C" void kernel_launch(void* const* d_in, const int* in_sizes, int n_in,
                              void* d_out, int out_size)
{
    const float* x     = (const float*)d_in[0];  // [2,2048,1024]
    const float* mask  = (const float*)d_in[1];  // [2,2048,2048]
    const float* W_qkv = (const float*)d_in[2];  // [1024,3072]
    const float* W_out = (const float*)d_in[3];  // [1024,1024]
    const float* b_out = (const float*)d_in[4];  // [1024]
    float* out = (float*)d_out;

    // One-time packing to fp16-half2 layouts
    pack_pairs<<<(4096 * 512 + 255) / 256, 256>>>(x, g_xh2, 4096 * 512);
    pack_rows<<<(512 * 3072 + 255) / 256, 256>>>(W_qkv, g_wqh2, 3072, 512 * 3072);
    pack_rows<<<(512 * 1024 + 255) / 256, 256>>>(W_out, g_woh2, 1024, 512 * 1024);

    const int gemm_smem = (64 * 36 + 32 * 68) * 4;   // 17920 B
    cudaFuncSetAttribute(gemm_h2, cudaFuncAttributeMaxDynamicSharedMemorySize, gemm_smem);

    // QKV projection -> packed q/k/v
    gemm_h2<<<dim3(3072 / 64, 4096 / 64), 128, gemm_smem>>>(
        g_xh2, g_wqh2, nullptr, nullptr, 3072, 0);

    // Attention -> packed z
    const int attn_smem = (64 * 36 + 32 * 68 + 64 * 36 + 64 * 68) * 4;  // 44544 B
    cudaFuncSetAttribute(attn_mma, cudaFuncAttributeMaxDynamicSharedMemorySize, attn_smem);
    attn_mma<<<dim3(LSEQ / 64, NB * NH), 128, attn_smem>>>(mask, g_zh2);

    // Output projection + bias -> fp32 out
    gemm_h2<<<dim3(1024 / 64, 4096 / 64), 128, gemm_smem>>>(
        g_zh2, g_woh2, b_out, out, 1024, 1);
}

// round 13
// speedup vs baseline: 1.2251x; 1.0445x over previous
#include <cuda_runtime.h>
#include <cuda_fp16.h>
#include <cstdint>
#include <math.h>

#define NH    16
#define DH    64
#define LSEQ  2048
#define NB    2
#define INNER 1024
#define QK_SCALE 0.125f

// Scratch (__device__ globals; allocation-free rule). u32 = packed half2.
__device__ uint32_t g_qh2[(size_t)NB*NH*LSEQ*32];   // [bh][l][dh/2] half2 along dh
__device__ uint32_t g_kh2[(size_t)NB*NH*LSEQ*32];
__device__ uint32_t g_vh2[(size_t)NB*NH*LSEQ*32];
__device__ uint32_t g_zh2[(size_t)4096*512];        // [b*l][inner/2] half2 along inner
__device__ uint32_t g_xh2[(size_t)4096*512];        // [b*l][dim/2]  half2 along k
__device__ uint32_t g_wqh2[(size_t)512*3072];       // [k/2][3072]   half2 = k-pair
__device__ uint32_t g_woh2[(size_t)512*1024];       // [k/2][1024]   half2 = k-pair

// ---------------------------------------------------------------------------
// Helpers (sm_80-baseline; safe on plain sm_103 target). NO cp.async.
// ---------------------------------------------------------------------------
__device__ __forceinline__ void mma16(float d[4], const uint32_t a[4],
                                      const uint32_t b[2]) {
    asm volatile(
        "mma.sync.aligned.m16n8k16.row.col.f32.f16.f16.f32 "
        "{%0,%1,%2,%3}, {%4,%5,%6,%7}, {%8,%9}, {%0,%1,%2,%3};"
        : "+f"(d[0]), "+f"(d[1]), "+f"(d[2]), "+f"(d[3])
        : "r"(a[0]), "r"(a[1]), "r"(a[2]), "r"(a[3]),
          "r"(b[0]), "r"(b[1]));
}
__device__ __forceinline__ uint32_t pack2(float lo, float hi) {
    __half2 h = __floats2half2_rn(lo, hi);
    return *(uint32_t*)&h;
}
__device__ __forceinline__ __half2 u2h(uint32_t v) {
    __half2 h; *(uint32_t*)&h = v; return h;
}
__device__ __forceinline__ uint32_t h2u(__half2 h) { return *(uint32_t*)&h; }

// ---------------------------------------------------------------------------
// Packing kernels (once per launch; ~50MB traffic total)
// ---------------------------------------------------------------------------
__global__ void pack_pairs(const float* __restrict__ src, uint32_t* __restrict__ dst,
                           int n)
{
    int i = blockIdx.x * blockDim.x + threadIdx.x;
    if (i < n) {
        float2 v = ((const float2*)src)[i];
        dst[i] = pack2(v.x, v.y);
    }
}
__global__ void pack_rows(const float* __restrict__ src, uint32_t* __restrict__ dst,
                          int N, int n)
{
    int i = blockIdx.x * blockDim.x + threadIdx.x;
    if (i < n) {
        int kp = i / N, c = i - kp * N;
        dst[i] = pack2(src[(size_t)(2 * kp) * N + c],
                       src[(size_t)(2 * kp + 1) * N + c]);
    }
}

// ---------------------------------------------------------------------------
// fp16 GEMM, round-10 structure (direct LDG->STS staging, 2 barriers/tile),
// packed operands. C[4096][Ncols] = A @ W.
// 128 threads = 4 warps; block tile 64x64; K-tile 128 (8 iterations).
// mode 0: pack+scatter C to qh2/kh2/vh2. mode 1: C + bias -> fp32 out.
// ---------------------------------------------------------------------------
__global__ __launch_bounds__(128) void gemm_h2(const uint32_t* __restrict__ A2,
                                               const uint32_t* __restrict__ W2,
                                               const float* __restrict__ bias,
                                               float* __restrict__ outp,
                                               int Ncols, int mode)
{
    extern __shared__ uint32_t sh[];
    uint32_t* As = sh;              // [64 m][68] u32 (64 kpairs)
    uint32_t* Bs = sh + 64 * 68;    // [64 kpair][68] u32

    const int tid  = threadIdx.x;
    const int lane = tid & 31;
    const int w    = tid >> 5;
    const int g    = lane >> 2;
    const int t    = lane & 3;
    const int m0   = blockIdx.y * 64;
    const int n0   = blockIdx.x * 64;
    const int rw   = w * 16;

    float acc[8][4];
    #pragma unroll
    for (int j = 0; j < 8; j++)
        #pragma unroll
        for (int r = 0; r < 4; r++) acc[j][r] = 0.f;

    #pragma unroll 1
    for (int kt = 0; kt < 8; kt++) {
        __syncthreads();
        // Stage A 64 rows x 64 u32, B 64 kpairs x 64 u32 (direct LDG->STS)
        #pragma unroll
        for (int i = 0; i < 8; i++) {
            int idx = tid + 128 * i;
            int r = idx >> 4, c4 = (idx & 15) * 4;
            uint4 a4 = *(const uint4*)&A2[(size_t)(m0 + r) * 512 + kt * 64 + c4];
            *(uint4*)&As[r * 68 + c4] = a4;
            uint4 b4 = *(const uint4*)&W2[(size_t)(kt * 64 + r) * Ncols + n0 + c4];
            *(uint4*)&Bs[r * 68 + c4] = b4;
        }
        __syncthreads();

        #pragma unroll
        for (int ks = 0; ks < 8; ks++) {
            uint32_t af[4];
            af[0] = As[(rw + g) * 68 + ks * 8 + t];
            af[1] = As[(rw + g + 8) * 68 + ks * 8 + t];
            af[2] = As[(rw + g) * 68 + ks * 8 + t + 4];
            af[3] = As[(rw + g + 8) * 68 + ks * 8 + t + 4];
            #pragma unroll
            for (int j = 0; j < 8; j++) {
                uint32_t bf[2];
                bf[0] = Bs[(ks * 8 + t) * 68 + j * 8 + g];
                bf[1] = Bs[(ks * 8 + t + 4) * 68 + j * 8 + g];
                mma16(acc[j], af, bf);
            }
        }
    }

    int r_lo = m0 + rw + g;
    int r_hi = r_lo + 8;
    #pragma unroll
    for (int j = 0; j < 8; j++) {
        int n = n0 + j * 8 + 2 * t;
        if (mode == 1) {
            float2 o0 = { acc[j][0] + bias[n], acc[j][1] + bias[n + 1] };
            float2 o1 = { acc[j][2] + bias[n], acc[j][3] + bias[n + 1] };
            *(float2*)&outp[(size_t)r_lo * 1024 + n] = o0;
            *(float2*)&outp[(size_t)r_hi * 1024 + n] = o1;
        } else {
            int three = n >> 10, rem = n & 1023, hh = rem >> 6, dd = rem & 63;
            uint32_t* base = (three == 0) ? g_qh2 : (three == 1) ? g_kh2 : g_vh2;
            int bb_lo = r_lo >> 11, ll_lo = r_lo & 2047;
            int bb_hi = r_hi >> 11, ll_hi = r_hi & 2047;
            base[(((size_t)(bb_lo * NH + hh) * LSEQ) + ll_lo) * 32 + (dd >> 1)] =
                pack2(acc[j][0], acc[j][1]);
            base[(((size_t)(bb_hi * NH + hh) * LSEQ) + ll_hi) * 32 + (dd >> 1)] =
                pack2(acc[j][2], acc[j][3]);
        }
    }
}

// ---------------------------------------------------------------------------
// Attention, round-10 structure (direct LDG->STS staging at loop top),
// packed q/k/v. No-max exact softmax; scale folded into exp (fp32).
// ---------------------------------------------------------------------------
__global__ __launch_bounds__(128) void attn_mma(const float* __restrict__ mask,
                                                uint32_t* __restrict__ z2)
{
    extern __shared__ uint32_t sh[];
    uint32_t* Ks2 = sh;                      // [64 seq][36] half2 along dh
    uint32_t* Vs2 = Ks2 + 64 * 36;           // [32 seqpair][68] half2 = seq pair
    uint32_t* Ps2 = Vs2 + 32 * 68;           // [64 q][36] half2 along seq
    float*    Ms  = (float*)(Ps2 + 64 * 36); // [64 q][68] fp32 mask

    const int tid  = threadIdx.x;
    const int lane = tid & 31;
    const int w    = tid >> 5;
    const int g    = lane >> 2;
    const int t    = lane & 3;
    const int qb   = blockIdx.x;
    const int bh   = blockIdx.y;
    const int bb   = bh >> 4, hh = bh & 15;
    const int q0   = qb * 64;
    const int rw   = w * 16;

    const uint32_t* qp = g_qh2 + ((size_t)bh * LSEQ + q0) * 32;
    const uint32_t* kp = g_kh2 + (size_t)bh * LSEQ * 32;
    const uint32_t* vp = g_vh2 + (size_t)bh * LSEQ * 32;
    const float*    mp = mask + (size_t)bb * LSEQ * LSEQ + (size_t)q0 * LSEQ;

    // Q fragments direct from packed gmem (scale applied later at exp)
    uint32_t qa[4][4];
    #pragma unroll
    for (int ks = 0; ks < 4; ks++) {
        const uint32_t* q_lo = qp + (rw + g) * 32;
        const uint32_t* q_hi = qp + (rw + g + 8) * 32;
        qa[ks][0] = q_lo[ks * 8 + t];
        qa[ks][1] = q_hi[ks * 8 + t];
        qa[ks][2] = q_lo[ks * 8 + t + 4];
        qa[ks][3] = q_hi[ks * 8 + t + 4];
    }

    float zacc[8][4];
    #pragma unroll
    for (int j = 0; j < 8; j++)
        #pragma unroll
        for (int r = 0; r < 4; r++) zacc[j][r] = 0.f;
    float sa_lo = 0.f, sa_hi = 0.f, sk_lo = 0.f, sk_hi = 0.f;

    #pragma unroll 1
    for (int jt = 0; jt < LSEQ / 64; jt++) {
        __syncthreads();     // prior compute done reading tiles
        // Stage K tile: 64 rows x 32 u32 (direct LDG->STS)
        #pragma unroll
        for (int i = 0; i < 4; i++) {
            int idx = tid + 128 * i;
            int r = idx >> 3, c4 = (idx & 7) * 4;
            uint4 k4 = *(const uint4*)&kp[(size_t)(jt * 64 + r) * 32 + c4];
            *(uint4*)&Ks2[r * 36 + c4] = k4;
        }
        // Stage V tile: seq-pair repack (cheap half2 shuffles)
        #pragma unroll
        for (int i = 0; i < 4; i++) {
            int idx = tid + 128 * i;
            int s = idx >> 4, c = (idx & 15) * 2;
            const uint32_t* v0 = &vp[(size_t)(jt * 64 + 2 * s) * 32 + c];
            uint2 a = *(const uint2*)v0;
            uint2 b = *(const uint2*)(v0 + 32);
            __half2 a0 = u2h(a.x), a1 = u2h(a.y), b0 = u2h(b.x), b1 = u2h(b.y);
            uint4 o = { h2u(__lows2half2(a0, b0)),  h2u(__highs2half2(a0, b0)),
                        h2u(__lows2half2(a1, b1)),  h2u(__highs2half2(a1, b1)) };
            *(uint4*)&Vs2[s * 68 + 2 * c] = o;
        }
        // Stage mask tile fp32
        #pragma unroll
        for (int i = 0; i < 8; i++) {
            int idx = tid + 128 * i;
            int r = idx >> 4, c4 = (idx & 15) * 4;
            float4 m4 = *(const float4*)&mp[(size_t)r * LSEQ + jt * 64 + c4];
            *(float4*)&Ms[r * 68 + c4] = m4;
        }
        __syncthreads();

        // S = Q K^T
        float sacc[8][4];
        #pragma unroll
        for (int j = 0; j < 8; j++)
            #pragma unroll
            for (int r = 0; r < 4; r++) sacc[j][r] = 0.f;
        #pragma unroll
        for (int ks = 0; ks < 4; ks++) {
            #pragma unroll
            for (int j = 0; j < 8; j++) {
                uint32_t bf[2];
                bf[0] = Ks2[(j * 8 + g) * 36 + ks * 8 + t];
                bf[1] = Ks2[(j * 8 + g) * 36 + ks * 8 + t + 4];
                mma16(sacc[j], qa[ks], bf);
            }
        }

        // exp(scale*s) + mask + row partial sums; write P (half2 along seq)
        #pragma unroll
        for (int j = 0; j < 8; j++) {
            float p0 = __expf(sacc[j][0] * QK_SCALE);
            float p1 = __expf(sacc[j][1] * QK_SCALE);
            float p2 = __expf(sacc[j][2] * QK_SCALE);
            float p3 = __expf(sacc[j][3] * QK_SCALE);
            float2 mlo = *(const float2*)&Ms[(rw + g) * 68 + j * 8 + 2 * t];
            float2 mhi = *(const float2*)&Ms[(rw + g + 8) * 68 + j * 8 + 2 * t];
            float w0 = p0 * mlo.x, w1 = p1 * mlo.y;
            float w2 = p2 * mhi.x, w3 = p3 * mhi.y;
            sa_lo += p0 + p1;  sa_hi += p2 + p3;
            sk_lo += w0 + w1;  sk_hi += w2 + w3;
            Ps2[(rw + g) * 36 + j * 4 + t]     = pack2(w0, w1);
            Ps2[(rw + g + 8) * 36 + j * 4 + t] = pack2(w2, w3);
        }
        __syncwarp();   // P rows are warp-private

        // zacc += P @ V
        #pragma unroll
        for (int ks = 0; ks < 4; ks++) {
            uint32_t pa4[4];
            pa4[0] = Ps2[(rw + g) * 36 + ks * 8 + t];
            pa4[1] = Ps2[(rw + g + 8) * 36 + ks * 8 + t];
            pa4[2] = Ps2[(rw + g) * 36 + ks * 8 + t + 4];
            pa4[3] = Ps2[(rw + g + 8) * 36 + ks * 8 + t + 4];
            #pragma unroll
            for (int j = 0; j < 8; j++) {
                uint32_t bf[2];
                bf[0] = Vs2[(ks * 8 + t) * 68 + j * 8 + g];
                bf[1] = Vs2[(ks * 8 + t + 4) * 68 + j * 8 + g];
                mma16(zacc[j], pa4, bf);
            }
        }
    }

    #pragma unroll
    for (int d = 1; d <= 2; d <<= 1) {
        sa_lo += __shfl_xor_sync(0xffffffffu, sa_lo, d);
        sa_hi += __shfl_xor_sync(0xffffffffu, sa_hi, d);
        sk_lo += __shfl_xor_sync(0xffffffffu, sk_lo, d);
        sk_hi += __shfl_xor_sync(0xffffffffu, sk_hi, d);
    }
    float inv_lo = 1.f / (sk_lo + 1e-10f * sa_lo);
    float inv_hi = 1.f / (sk_hi + 1e-10f * sa_hi);

    size_t row_lo = (size_t)bb * LSEQ + q0 + rw + g;
    size_t row_hi = row_lo + 8;
    #pragma unroll
    for (int j = 0; j < 8; j++) {
        int c = hh * 32 + j * 4 + t;
        z2[row_lo * 512 + c] = pack2(zacc[j][0] * inv_lo, zacc[j][1] * inv_lo);
        z2[row_hi * 512 + c] = pack2(zacc[j][2] * inv_hi, zacc[j][3] * inv_hi);
    }
}

// ---------------------------------------------------------------------------
extern "C" void kernel_launch(void* const* d_in, const int* in_sizes, int n_in,
                              void* d_out, int out_size)
{
    const float* x     = (const float*)d_in[0];  // [2,2048,1024]
    const float* mask  = (const float*)d_in[1];  // [2,2048,2048]
    const float* W_qkv = (const float*)d_in[2];  // [1024,3072]
    const float* W_out = (const float*)d_in[3];  // [1024,1024]
    const float* b_out = (const float*)d_in[4];  // [1024]
    float* out = (float*)d_out;

    // One-time packing to fp16-half2 layouts
    pack_pairs<<<(4096 * 512 + 255) / 256, 256>>>(x, g_xh2, 4096 * 512);
    pack_rows<<<(512 * 3072 + 255) / 256, 256>>>(W_qkv, g_wqh2, 3072, 512 * 3072);
    pack_rows<<<(512 * 1024 + 255) / 256, 256>>>(W_out, g_woh2, 1024, 512 * 1024);

    const int gemm_smem = (64 * 68 + 64 * 68) * 4;   // 34816 B
    cudaFuncSetAttribute(gemm_h2, cudaFuncAttributeMaxDynamicSharedMemorySize, gemm_smem);

    // QKV projection -> packed q/k/v
    gemm_h2<<<dim3(3072 / 64, 4096 / 64), 128, gemm_smem>>>(
        g_xh2, g_wqh2, nullptr, nullptr, 3072, 0);

    // Attention -> packed z
    const int attn_smem = (64 * 36 + 32 * 68 + 64 * 36 + 64 * 68) * 4;  // 44544 B
    cudaFuncSetAttribute(attn_mma, cudaFuncAttributeMaxDynamicSharedMemorySize, attn_smem);
    attn_mma<<<dim3(LSEQ / 64, NB * NH), 128, attn_smem>>>(mask, g_zh2);

    // Output projection + bias -> fp32 out
    gemm_h2<<<dim3(1024 / 64, 4096 / 64), 128, gemm_smem>>>(
        g_zh2, g_woh2, b_out, out, 1024, 1);
}

// round 14
// speedup vs baseline: 3.1352x; 2.5592x over previous
#include <cuda_runtime.h>
#include <cuda_fp16.h>
#include <cstdint>
#include <math.h>

#define NH    16
#define DH    64
#define LSEQ  2048
#define NB    2
#define INNER 1024
#define QK_SCALE 0.125f

// Scratch (__device__ globals; allocation-free rule) — fp32, round-10 proven.
__device__ float g_q[(size_t)NB*NH*LSEQ*DH];   // [b,h,l,dh]
__device__ float g_k[(size_t)NB*NH*LSEQ*DH];
__device__ float g_v[(size_t)NB*NH*LSEQ*DH];
__device__ float g_z[(size_t)NB*LSEQ*INNER];   // [b,l,h*dh]

// ---------------------------------------------------------------------------
// Helpers (sm_80-baseline; safe on plain sm_103 target). NO cp.async.
// ---------------------------------------------------------------------------
__device__ __forceinline__ void mma16(float d[4], const uint32_t a[4],
                                      const uint32_t b[2]) {
    asm volatile(
        "mma.sync.aligned.m16n8k16.row.col.f32.f16.f16.f32 "
        "{%0,%1,%2,%3}, {%4,%5,%6,%7}, {%8,%9}, {%0,%1,%2,%3};"
        : "+f"(d[0]), "+f"(d[1]), "+f"(d[2]), "+f"(d[3])
        : "r"(a[0]), "r"(a[1]), "r"(a[2]), "r"(a[3]),
          "r"(b[0]), "r"(b[1]));
}
__device__ __forceinline__ uint32_t pack2(float lo, float hi) {
    __half2 h = __floats2half2_rn(lo, hi);
    return *(uint32_t*)&h;
}

// ---------------------------------------------------------------------------
// fp16 mma GEMM (BYTE-IDENTICAL to round 10's proven gemm64h).
// C[4096][Ncols] = A[4096][1024] @ W[1024][Ncols] (W native layout).
// 128 threads = 4 warps; block tile 64x64; K-tile 128.
// mode 0: scatter C to q/k/v (fp32). mode 1: C + bias -> out.
// ---------------------------------------------------------------------------
__global__ __launch_bounds__(128) void gemm64h(const float* __restrict__ A,
                                               const float* __restrict__ W,
                                               const float* __restrict__ bias,
                                               float* __restrict__ outp,
                                               int Ncols, int mode)
{
    extern __shared__ uint32_t sh[];
    uint32_t* As2 = sh;              // [64][68] u32 (half2 pairs along k)
    uint32_t* Bs2 = sh + 64 * 68;    // [64][68] u32 (half2 = two k-rows)

    const int tid  = threadIdx.x;
    const int lane = tid & 31;
    const int w    = tid >> 5;
    const int g    = lane >> 2;
    const int t    = lane & 3;
    const int m0   = blockIdx.y * 64;
    const int n0   = blockIdx.x * 64;
    const int rw   = w * 16;

    float acc[8][4];
    #pragma unroll
    for (int j = 0; j < 8; j++)
        #pragma unroll
        for (int r = 0; r < 4; r++) acc[j][r] = 0.f;

    #pragma unroll 1
    for (int kt = 0; kt < 8; kt++) {
        __syncthreads();
        // Stage A 64x128 (fp32 -> half2 pairs along k)
        #pragma unroll
        for (int i = 0; i < 16; i++) {
            int idx = tid + 128 * i;
            int r = idx >> 5, c = (idx & 31) * 4;
            float4 a4 = *(const float4*)&A[(size_t)(m0 + r) * 1024 + kt * 128 + c];
            uint2 p = { pack2(a4.x, a4.y), pack2(a4.z, a4.w) };
            *(uint2*)&As2[r * 68 + (c >> 1)] = p;
        }
        // Stage B 128x64: pack rows 2k,2k+1 into half2
        #pragma unroll
        for (int i = 0; i < 8; i++) {
            int idx = tid + 128 * i;
            int kp = idx >> 4, nc = (idx & 15) * 4;
            const float* wr = W + (size_t)(kt * 128 + 2 * kp) * Ncols + n0 + nc;
            float4 e = *(const float4*)wr;
            float4 o = *(const float4*)(wr + Ncols);
            uint4 p = { pack2(e.x, o.x), pack2(e.y, o.y),
                        pack2(e.z, o.z), pack2(e.w, o.w) };
            *(uint4*)&Bs2[kp * 68 + nc] = p;
        }
        __syncthreads();

        #pragma unroll
        for (int ks = 0; ks < 8; ks++) {
            uint32_t af[4];
            af[0] = As2[(rw + g) * 68 + ks * 8 + t];
            af[1] = As2[(rw + g + 8) * 68 + ks * 8 + t];
            af[2] = As2[(rw + g) * 68 + ks * 8 + t + 4];
            af[3] = As2[(rw + g + 8) * 68 + ks * 8 + t + 4];
            #pragma unroll
            for (int j = 0; j < 8; j++) {
                uint32_t bf[2];
                bf[0] = Bs2[(ks * 8 + t) * 68 + j * 8 + g];
                bf[1] = Bs2[(ks * 8 + t + 4) * 68 + j * 8 + g];
                mma16(acc[j], af, bf);
            }
        }
    }

    int r_lo = m0 + rw + g;
    int r_hi = r_lo + 8;
    #pragma unroll
    for (int j = 0; j < 8; j++) {
        int n = n0 + j * 8 + 2 * t;
        if (mode == 1) {
            float2 o0 = { acc[j][0] + bias[n], acc[j][1] + bias[n + 1] };
            float2 o1 = { acc[j][2] + bias[n], acc[j][3] + bias[n + 1] };
            *(float2*)&outp[(size_t)r_lo * 1024 + n] = o0;
            *(float2*)&outp[(size_t)r_hi * 1024 + n] = o1;
        } else {
            int three = n >> 10, rem = n & 1023, hh = rem >> 6, dd = rem & 63;
            float* base = (three == 0) ? g_q : (three == 1) ? g_k : g_v;
            int bb_lo = r_lo >> 11, ll_lo = r_lo & 2047;
            int bb_hi = r_hi >> 11, ll_hi = r_hi & 2047;
            float2 o0 = { acc[j][0], acc[j][1] };
            float2 o1 = { acc[j][2], acc[j][3] };
            *(float2*)&base[(((size_t)(bb_lo * NH + hh) * LSEQ) + ll_lo) * DH + dd] = o0;
            *(float2*)&base[(((size_t)(bb_hi * NH + hh) * LSEQ) + ll_hi) * DH + dd] = o1;
        }
    }
}

// ---------------------------------------------------------------------------
// Attention (round-10 math) with two edits:
//   1) BM=128 (8 warps, 256 threads) — K/V staging amortized over 2x q rows
//   2) mask read by direct LDG at fragment coords (no smem round-trip)
// No-max exact softmax: p=exp(s); z=(p*mask)@V / (sum(p*mask)+eps*sum(p)).
// ---------------------------------------------------------------------------
__global__ __launch_bounds__(256) void attn_mma(const float* __restrict__ mask,
                                                float* __restrict__ z)
{
    extern __shared__ uint32_t sh[];
    uint32_t* Ks2 = sh;                      // [64 seq][36] half2 along dh
    uint32_t* Vs2 = Ks2 + 64 * 36;           // [32 seqpair][68] half2 = seq pair
    uint32_t* Ps2 = Vs2 + 32 * 68;           // [128 q][36] half2 along seq

    const int tid  = threadIdx.x;
    const int lane = tid & 31;
    const int w    = tid >> 5;               // 0..7
    const int g    = lane >> 2;
    const int t    = lane & 3;
    const int qb   = blockIdx.x;
    const int bh   = blockIdx.y;
    const int bb   = bh >> 4, hh = bh & 15;
    const int q0   = qb * 128;
    const int rw   = w * 16;

    const float* qp = g_q + ((size_t)bh * LSEQ + q0) * DH;
    const float* kp = g_k + (size_t)bh * LSEQ * DH;
    const float* vp = g_v + (size_t)bh * LSEQ * DH;
    const float* mrow_lo = mask + ((size_t)bb * LSEQ + q0 + rw + g) * LSEQ;
    const float* mrow_hi = mrow_lo + (size_t)8 * LSEQ;

    // Q fragments direct from fp32 gmem, scale folded (round-10 pattern)
    uint32_t qa[4][4];
    #pragma unroll
    for (int ks = 0; ks < 4; ks++) {
        const float* q_lo = qp + (rw + g) * 64 + ks * 16 + 2 * t;
        const float* q_hi = q_lo + 8 * 64;
        float2 a = *(const float2*)q_lo;
        float2 b = *(const float2*)q_hi;
        float2 c = *(const float2*)(q_lo + 8);
        float2 d = *(const float2*)(q_hi + 8);
        qa[ks][0] = pack2(QK_SCALE * a.x, QK_SCALE * a.y);
        qa[ks][1] = pack2(QK_SCALE * b.x, QK_SCALE * b.y);
        qa[ks][2] = pack2(QK_SCALE * c.x, QK_SCALE * c.y);
        qa[ks][3] = pack2(QK_SCALE * d.x, QK_SCALE * d.y);
    }

    float zacc[8][4];
    #pragma unroll
    for (int j = 0; j < 8; j++)
        #pragma unroll
        for (int r = 0; r < 4; r++) zacc[j][r] = 0.f;
    float sa_lo = 0.f, sa_hi = 0.f, sk_lo = 0.f, sk_hi = 0.f;

    #pragma unroll 1
    for (int jt = 0; jt < LSEQ / 64; jt++) {
        __syncthreads();   // all warps done reading Ks2/Vs2 from prior iter
        // Stage K 64x64 (fp32 -> half2 along dh): 1024 float4, 256 threads
        #pragma unroll
        for (int i = 0; i < 4; i++) {
            int idx = tid + 256 * i;
            int r = idx >> 4, c = (idx & 15) * 4;
            float4 k4 = *(const float4*)&kp[(size_t)(jt * 64 + r) * 64 + c];
            uint2 p = { pack2(k4.x, k4.y), pack2(k4.z, k4.w) };
            *(uint2*)&Ks2[r * 36 + (c >> 1)] = p;
        }
        // Stage V 64x64: pack seq rows 2s,2s+1 into half2: 512 entries
        #pragma unroll
        for (int i = 0; i < 2; i++) {
            int idx = tid + 256 * i;
            int s = idx >> 4, d = (idx & 15) * 4;
            const float* vr = vp + (size_t)(jt * 64 + 2 * s) * 64 + d;
            float4 e = *(const float4*)vr;
            float4 o = *(const float4*)(vr + 64);
            uint4 p = { pack2(e.x, o.x), pack2(e.y, o.y),
                        pack2(e.z, o.z), pack2(e.w, o.w) };
            *(uint4*)&Vs2[s * 68 + d] = p;
        }
        __syncthreads();

        // S = Q K^T (scaled)
        float sacc[8][4];
        #pragma unroll
        for (int j = 0; j < 8; j++)
            #pragma unroll
            for (int r = 0; r < 4; r++) sacc[j][r] = 0.f;
        #pragma unroll
        for (int ks = 0; ks < 4; ks++) {
            #pragma unroll
            for (int j = 0; j < 8; j++) {
                uint32_t bf[2];
                bf[0] = Ks2[(j * 8 + g) * 36 + ks * 8 + t];
                bf[1] = Ks2[(j * 8 + g) * 36 + ks * 8 + t + 4];
                mma16(sacc[j], qa[ks], bf);
            }
        }

        // exp + mask (direct LDG at fragment coords) + row sums; write P
        #pragma unroll
        for (int j = 0; j < 8; j++) {
            float p0 = __expf(sacc[j][0]);
            float p1 = __expf(sacc[j][1]);
            float p2 = __expf(sacc[j][2]);
            float p3 = __expf(sacc[j][3]);
            float2 mlo = *(const float2*)&mrow_lo[jt * 64 + j * 8 + 2 * t];
            float2 mhi = *(const float2*)&mrow_hi[jt * 64 + j * 8 + 2 * t];
            float w0 = p0 * mlo.x, w1 = p1 * mlo.y;
            float w2 = p2 * mhi.x, w3 = p3 * mhi.y;
            sa_lo += p0 + p1;  sa_hi += p2 + p3;
            sk_lo += w0 + w1;  sk_hi += w2 + w3;
            Ps2[(rw + g) * 36 + j * 4 + t]     = pack2(w0, w1);
            Ps2[(rw + g + 8) * 36 + j * 4 + t] = pack2(w2, w3);
        }
        __syncwarp();   // P rows are warp-private

        // zacc += P @ V
        #pragma unroll
        for (int ks = 0; ks < 4; ks++) {
            uint32_t pa4[4];
            pa4[0] = Ps2[(rw + g) * 36 + ks * 8 + t];
            pa4[1] = Ps2[(rw + g + 8) * 36 + ks * 8 + t];
            pa4[2] = Ps2[(rw + g) * 36 + ks * 8 + t + 4];
            pa4[3] = Ps2[(rw + g + 8) * 36 + ks * 8 + t + 4];
            #pragma unroll
            for (int j = 0; j < 8; j++) {
                uint32_t bf[2];
                bf[0] = Vs2[(ks * 8 + t) * 68 + j * 8 + g];
                bf[1] = Vs2[(ks * 8 + t + 4) * 68 + j * 8 + g];
                mma16(zacc[j], pa4, bf);
            }
        }
    }

    #pragma unroll
    for (int d = 1; d <= 2; d <<= 1) {
        sa_lo += __shfl_xor_sync(0xffffffffu, sa_lo, d);
        sa_hi += __shfl_xor_sync(0xffffffffu, sa_hi, d);
        sk_lo += __shfl_xor_sync(0xffffffffu, sk_lo, d);
        sk_hi += __shfl_xor_sync(0xffffffffu, sk_hi, d);
    }
    float inv_lo = 1.f / (sk_lo + 1e-10f * sa_lo);
    float inv_hi = 1.f / (sk_hi + 1e-10f * sa_hi);

    size_t row_lo = (size_t)bb * LSEQ + q0 + rw + g;
    size_t row_hi = row_lo + 8;
    #pragma unroll
    for (int j = 0; j < 8; j++) {
        int dh = hh * 64 + j * 8 + 2 * t;
        float2 o0 = { zacc[j][0] * inv_lo, zacc[j][1] * inv_lo };
        float2 o1 = { zacc[j][2] * inv_hi, zacc[j][3] * inv_hi };
        *(float2*)&z[row_lo * INNER + dh] = o0;
        *(float2*)&z[row_hi * INNER + dh] = o1;
    }
}

// ---------------------------------------------------------------------------
extern "C" void kernel_launch(void* const* d_in, const int* in_sizes, int n_in,
                              void* d_out, int out_size)
{
    const float* x     = (const float*)d_in[0];  // [2,2048,1024]
    const float* mask  = (const float*)d_in[1];  // [2,2048,2048]
    const float* W_qkv = (const float*)d_in[2];  // [1024,3072]
    const float* W_out = (const float*)d_in[3];  // [1024,1024]
    const float* b_out = (const float*)d_in[4];  // [1024]
    float* out = (float*)d_out;

    const int gemm_smem = (64 * 68 + 64 * 68) * 4;   // 34816 B
    cudaFuncSetAttribute(gemm64h, cudaFuncAttributeMaxDynamicSharedMemorySize, gemm_smem);

    // QKV projection -> fp32 q/k/v (W in native [k][n] layout)
    gemm64h<<<dim3(3072 / 64, 4096 / 64), 128, gemm_smem>>>(
        x, W_qkv, nullptr, nullptr, 3072, 0);

    // Attention (BM=128, 256 threads, mask via direct LDG)
    const int attn_smem = (64 * 36 + 32 * 68 + 128 * 36) * 4;  // 36352 B
    cudaFuncSetAttribute(attn_mma, cudaFuncAttributeMaxDynamicSharedMemorySize, attn_smem);
    attn_mma<<<dim3(LSEQ / 128, NB * NH), 256, attn_smem>>>(mask, g_z);

    // Output projection + bias
    gemm64h<<<dim3(1024 / 64, 4096 / 64), 128, gemm_smem>>>(
        g_z, W_out, b_out, out, 1024, 1);
}